// round 9
// baseline (speedup 1.0000x reference)
#include <cuda_runtime.h>
#include <cuda_fp16.h>

#define NMAX_NODES 50000
#define NMAX_EDGES 800000

// Scratch (device globals; no allocation allowed)
__device__ __half g_zh[NMAX_NODES * 128];
__device__ float  g_ssrc[NMAX_NODES];
__device__ float  g_sdst[NMAX_NODES];
__device__ float  g_se[NMAX_EDGES];
__device__ int    g_deg[NMAX_NODES];
__device__ int    g_start[NMAX_NODES];
__device__ int    g_cursor[NMAX_NODES];
__device__ uint2  g_pe[NMAX_EDGES];   // packed (src, ssrc[src]+s_e), dst-sorted

__device__ __forceinline__ float warp_sum(float v) {
#pragma unroll
    for (int o = 16; o; o >>= 1) v += __shfl_xor_sync(0xffffffffu, v, o);
    return v;
}

__device__ __forceinline__ unsigned smem_u32(const void* p) {
    unsigned a;
    asm("{ .reg .u64 t; cvta.to.shared.u64 t, %1; cvt.u32.u64 %0, t; }"
        : "=r"(a) : "l"(p));
    return a;
}

__device__ __forceinline__ void ldsm_x4(unsigned& r0, unsigned& r1, unsigned& r2,
                                        unsigned& r3, unsigned addr) {
    asm volatile("ldmatrix.sync.aligned.m8n8.x4.shared.b16 {%0,%1,%2,%3}, [%4];"
                 : "=r"(r0), "=r"(r1), "=r"(r2), "=r"(r3) : "r"(addr));
}
__device__ __forceinline__ void ldsm_x2(unsigned& r0, unsigned& r1, unsigned addr) {
    asm volatile("ldmatrix.sync.aligned.m8n8.x2.shared.b16 {%0,%1}, [%2];"
                 : "=r"(r0), "=r"(r1) : "r"(addr));
}
__device__ __forceinline__ void mma16816(float* c, const unsigned* a, const unsigned* b) {
    asm volatile(
        "mma.sync.aligned.m16n8k16.row.col.f32.f16.f16.f32 "
        "{%0,%1,%2,%3}, {%4,%5,%6,%7}, {%8,%9}, {%0,%1,%2,%3};"
        : "+f"(c[0]), "+f"(c[1]), "+f"(c[2]), "+f"(c[3])
        : "r"(a[0]), "r"(a[1]), "r"(a[2]), "r"(a[3]), "r"(b[0]), "r"(b[1]));
}

__device__ __forceinline__ unsigned pack_h2(float a, float b) {
    __half2 h = __floats2half2_rn(a, b);
    return *reinterpret_cast<unsigned*>(&h);
}

// ---------------------------------------------------------------------------
// K1: z = nfeats @ W_fc^T via HMMA, fp32 inputs converted inline.
// Fused epilogue: fp16 z, s_src/s_dst dots, AND deg zeroing.
// ---------------------------------------------------------------------------
#define ASTR 136                 // padded row stride in halfs
#define GEMMH_SMEM (2 * 128 * ASTR * 2 + 288 * 4)

__global__ __launch_bounds__(256) void k_gemm_h(const float* __restrict__ nf,
                                                const float* __restrict__ W,
                                                const float* __restrict__ Wa,
                                                int n_nodes) {
    extern __shared__ __half hsm[];
    __half* sA = hsm;             // [128][ASTR]
    __half* sB = hsm + 128 * ASTR;
    float* sWa = reinterpret_cast<float*>(hsm + 2 * 128 * ASTR);  // [288]
    int tid = threadIdx.x;
    int rowBase = blockIdx.x * 128;

    if (tid < 144) {
        ((float2*)sWa)[tid] = ((const float2*)Wa)[tid];  // 288 floats
    }
#pragma unroll
    for (int c = tid; c < 2048; c += 256) {
        int row = c >> 4;
        int col16 = c & 15;                 // 8-half chunk
        int r = rowBase + row;
        uint4 hv = make_uint4(0u, 0u, 0u, 0u);
        if (r < n_nodes) {
            float4 v0 = ((const float4*)nf)[(size_t)r * 32 + col16 * 2];
            float4 v1 = ((const float4*)nf)[(size_t)r * 32 + col16 * 2 + 1];
            hv.x = pack_h2(v0.x, v0.y);
            hv.y = pack_h2(v0.z, v0.w);
            hv.z = pack_h2(v1.x, v1.y);
            hv.w = pack_h2(v1.z, v1.w);
        }
        *reinterpret_cast<uint4*>(sA + row * ASTR + col16 * 8) = hv;
        float4 w0 = ((const float4*)W)[row * 32 + col16 * 2];
        float4 w1 = ((const float4*)W)[row * 32 + col16 * 2 + 1];
        uint4 wv;
        wv.x = pack_h2(w0.x, w0.y);
        wv.y = pack_h2(w0.z, w0.w);
        wv.z = pack_h2(w1.x, w1.y);
        wv.w = pack_h2(w1.z, w1.w);
        *reinterpret_cast<uint4*>(sB + row * ASTR + col16 * 8) = wv;
    }
    __syncthreads();

    int warp = tid >> 5;
    int lane = tid & 31;
    int m0 = warp * 16;

    float acc[16][4];
#pragma unroll
    for (int nt = 0; nt < 16; nt++)
#pragma unroll
        for (int j = 0; j < 4; j++) acc[nt][j] = 0.f;

    unsigned aBase = smem_u32(sA) + ((m0 + (lane & 15)) * ASTR + ((lane >> 4) << 3)) * 2;
    unsigned bBase = smem_u32(sB) + ((lane & 7) * ASTR + (((lane >> 3) & 1) << 3)) * 2;

#pragma unroll
    for (int ks = 0; ks < 8; ks++) {
        unsigned a[4];
        ldsm_x4(a[0], a[1], a[2], a[3], aBase + ks * 32);
#pragma unroll
        for (int nt = 0; nt < 16; nt++) {
            unsigned b[2];
            ldsm_x2(b[0], b[1], bBase + (nt * 8 * ASTR) * 2 + ks * 32);
            mma16816(acc[nt], a, b);
        }
    }

    // Epilogue: z (fp16) + fused s_src/s_dst partial dots + deg zeroing
    int gr = lane >> 2;
    int colq = (lane & 3) * 2;
    int r0 = rowBase + m0 + gr;
    int r1 = r0 + 8;
    float v1a = 0.f, v2a = 0.f, v1b = 0.f, v2b = 0.f;
#pragma unroll
    for (int nt = 0; nt < 16; nt++) {
        int col = nt * 8 + colq;
        float as0 = sWa[col], as1 = sWa[col + 1];
        float ad0 = sWa[160 + col], ad1 = sWa[161 + col];
        v1a += acc[nt][0] * as0 + acc[nt][1] * as1;
        v2a += acc[nt][0] * ad0 + acc[nt][1] * ad1;
        v1b += acc[nt][2] * as0 + acc[nt][3] * as1;
        v2b += acc[nt][2] * ad0 + acc[nt][3] * ad1;
        if (r0 < n_nodes) {
            unsigned h = pack_h2(acc[nt][0], acc[nt][1]);
            *reinterpret_cast<unsigned*>(g_zh + (size_t)r0 * 128 + col) = h;
        }
        if (r1 < n_nodes) {
            unsigned h = pack_h2(acc[nt][2], acc[nt][3]);
            *reinterpret_cast<unsigned*>(g_zh + (size_t)r1 * 128 + col) = h;
        }
    }
#pragma unroll
    for (int o = 1; o <= 2; o <<= 1) {
        v1a += __shfl_xor_sync(0xffffffffu, v1a, o);
        v2a += __shfl_xor_sync(0xffffffffu, v2a, o);
        v1b += __shfl_xor_sync(0xffffffffu, v1b, o);
        v2b += __shfl_xor_sync(0xffffffffu, v2b, o);
    }
    if ((lane & 3) == 0) {
        if (r0 < n_nodes) { g_ssrc[r0] = v1a; g_sdst[r0] = v2a; g_deg[r0] = 0; }
        if (r1 < n_nodes) { g_ssrc[r1] = v1b; g_sdst[r1] = v2b; g_deg[r1] = 0; }
    }
}

// ---------------------------------------------------------------------------
// K2: coalesced s_e = efeats·a_e + deg histogram. Warp = 32 edges (MLP=8).
// ---------------------------------------------------------------------------
__global__ __launch_bounds__(256) void k_se_hist(const float* __restrict__ ef,
                                                 const float* __restrict__ Wa,
                                                 const int* __restrict__ dst,
                                                 int n_edges) {
    __shared__ float sa[32];
    if (threadIdx.x < 32) sa[threadIdx.x] = Wa[128 + threadIdx.x];  // a_e
    __syncthreads();
    int warp = (blockIdx.x * blockDim.x + threadIdx.x) >> 5;
    int lane = threadIdx.x & 31;
    int sub = lane >> 3;
    int g = lane & 7;
    int e0 = warp * 32 + sub;

    float4 x[8];
#pragma unroll
    for (int u = 0; u < 8; u++) {
        int e = e0 + u * 4;
        x[u] = (e < n_edges) ? __ldg((const float4*)ef + (size_t)e * 8 + g)
                             : make_float4(0.f, 0.f, 0.f, 0.f);
    }
    float c0 = sa[g * 4], c1 = sa[g * 4 + 1], c2 = sa[g * 4 + 2], c3 = sa[g * 4 + 3];
    float v[8];
#pragma unroll
    for (int u = 0; u < 8; u++)
        v[u] = x[u].x * c0 + x[u].y * c1 + x[u].z * c2 + x[u].w * c3;
#pragma unroll
    for (int u = 0; u < 8; u++) {
        v[u] += __shfl_xor_sync(0xffffffffu, v[u], 4);
        v[u] += __shfl_xor_sync(0xffffffffu, v[u], 2);
        v[u] += __shfl_xor_sync(0xffffffffu, v[u], 1);
    }
    if (g == 0) {
#pragma unroll
        for (int u = 0; u < 8; u++) {
            int e = e0 + u * 4;
            if (e < n_edges) {
                g_se[e] = v[u];
                atomicAdd(&g_deg[dst[e]], 1);
            }
        }
    }
}

// ---------------------------------------------------------------------------
// K3: single-block exclusive scan of deg -> start/cursor (1024 threads)
// ---------------------------------------------------------------------------
__global__ __launch_bounds__(1024) void k_scan_all(int n) {
    __shared__ int s[1024];
    int t = threadIdx.x;
    int ch = (n + 1023) >> 10;          // chunk size per thread
    int b0 = t * ch;
    int b1 = min(b0 + ch, n);
    int sum = 0;
#pragma unroll 4
    for (int i = b0; i < b1; i++) sum += g_deg[i];
    s[t] = sum;
    __syncthreads();
#pragma unroll
    for (int off = 1; off < 1024; off <<= 1) {
        int v = (t >= off) ? s[t - off] : 0;
        __syncthreads();
        s[t] += v;
        __syncthreads();
    }
    int run = s[t] - sum;               // exclusive prefix of this chunk
#pragma unroll 4
    for (int i = b0; i < b1; i++) {
        g_start[i] = run;
        g_cursor[i] = run;
        run += g_deg[i];
    }
}

// ---------------------------------------------------------------------------
// K4: per edge: t = ssrc[src] + s_e; place packed (src, t) into dst-sorted
//     position. (exp/leaky/sdst deferred to k_agg, where sdst is uniform.)
// ---------------------------------------------------------------------------
__global__ __launch_bounds__(256) void k_edge_place(const int* __restrict__ src,
                                                    const int* __restrict__ dst,
                                                    int n_edges) {
    int e = blockIdx.x * blockDim.x + threadIdx.x;
    if (e >= n_edges) return;
    int s = src[e];
    int d = dst[e];
    float t = __ldg(&g_ssrc[s]) + g_se[e];
    int pos = atomicAdd(&g_cursor[d], 1);
    uint2 v;
    v.x = (unsigned)s;
    v.y = __float_as_uint(t);
    g_pe[pos] = v;
}

// ---------------------------------------------------------------------------
// K5: warp per dst node: w_e = exp(leaky(t_e + sdst[d])) vectorized;
//     h[d] = (sum w_e * zh[src_e]) / (sum w_e). Gather loop unrolled x4.
// ---------------------------------------------------------------------------
__global__ __launch_bounds__(256) void k_agg(float* __restrict__ out, int n_nodes) {
    int d = (blockIdx.x * blockDim.x + threadIdx.x) >> 5;
    int lane = threadIdx.x & 31;
    if (d >= n_nodes) return;
    int start = g_start[d];
    int deg = g_deg[d];
    float sdst_d = g_sdst[d];
    float4 acc = make_float4(0.f, 0.f, 0.f, 0.f);
    float wsum = 0.f;

    for (int i = 0; i < deg; i += 32) {
        int s = 0;
        float wv = 0.f;
        if (i + lane < deg) {
            uint2 p = g_pe[start + i + lane];
            s = (int)p.x;
            float ev = __uint_as_float(p.y) + sdst_d;
            ev = (ev > 0.f) ? ev : 0.01f * ev;
            wv = __expf(ev);
        }
        wsum += wv;
        int cnt = min(32, deg - i);
        int j = 0;
        for (; j + 4 <= cnt; j += 4) {
            int s0 = __shfl_sync(0xffffffffu, s, j);
            int s1 = __shfl_sync(0xffffffffu, s, j + 1);
            int s2 = __shfl_sync(0xffffffffu, s, j + 2);
            int s3 = __shfl_sync(0xffffffffu, s, j + 3);
            float w0 = __shfl_sync(0xffffffffu, wv, j);
            float w1 = __shfl_sync(0xffffffffu, wv, j + 1);
            float w2 = __shfl_sync(0xffffffffu, wv, j + 2);
            float w3 = __shfl_sync(0xffffffffu, wv, j + 3);
            uint2 h0 = *reinterpret_cast<const uint2*>(g_zh + (size_t)s0 * 128 + lane * 4);
            uint2 h1 = *reinterpret_cast<const uint2*>(g_zh + (size_t)s1 * 128 + lane * 4);
            uint2 h2 = *reinterpret_cast<const uint2*>(g_zh + (size_t)s2 * 128 + lane * 4);
            uint2 h3 = *reinterpret_cast<const uint2*>(g_zh + (size_t)s3 * 128 + lane * 4);
#define ACC_EDGE(hz, wj)                                                   \
            {                                                              \
                float2 f01 = __half22float2(*reinterpret_cast<__half2*>(&hz.x)); \
                float2 f23 = __half22float2(*reinterpret_cast<__half2*>(&hz.y)); \
                acc.x += (wj) * f01.x;                                     \
                acc.y += (wj) * f01.y;                                     \
                acc.z += (wj) * f23.x;                                     \
                acc.w += (wj) * f23.y;                                     \
            }
            ACC_EDGE(h0, w0)
            ACC_EDGE(h1, w1)
            ACC_EDGE(h2, w2)
            ACC_EDGE(h3, w3)
        }
        for (; j < cnt; j++) {
            int sj = __shfl_sync(0xffffffffu, s, j);
            float wj = __shfl_sync(0xffffffffu, wv, j);
            uint2 hz = *reinterpret_cast<const uint2*>(g_zh + (size_t)sj * 128 + lane * 4);
            ACC_EDGE(hz, wj)
        }
#undef ACC_EDGE
    }
    wsum = warp_sum(wsum);
    float dinv = (wsum > 0.f) ? 1.0f / wsum : 0.f;
    ((float4*)out)[d * 32 + lane] =
        make_float4(acc.x * dinv, acc.y * dinv, acc.z * dinv, acc.w * dinv);
}

// ---------------------------------------------------------------------------
extern "C" void kernel_launch(void* const* d_in, const int* in_sizes, int n_in,
                              void* d_out, int out_size) {
    const float* nf  = (const float*)d_in[0];
    const float* ef  = (const float*)d_in[1];
    const float* Wfc = (const float*)d_in[2];
    const float* Wa  = (const float*)d_in[3];
    const int*   src = (const int*)d_in[4];
    const int*   dst = (const int*)d_in[5];
    float* out = (float*)d_out;

    int n_nodes = in_sizes[0] / 128;
    int n_edges = in_sizes[4];

    cudaFuncSetAttribute(k_gemm_h, cudaFuncAttributeMaxDynamicSharedMemorySize, GEMMH_SMEM);

    k_gemm_h<<<(n_nodes + 127) / 128, 256, GEMMH_SMEM>>>(nf, Wfc, Wa, n_nodes);
    k_se_hist<<<(n_edges + 255) / 256, 256>>>(ef, Wa, dst, n_edges);
    k_scan_all<<<1, 1024>>>(n_nodes);
    k_edge_place<<<(n_edges + 255) / 256, 256>>>(src, dst, n_edges);
    k_agg<<<(n_nodes + 7) / 8, 256>>>(out, n_nodes);
}

// round 10
// speedup vs baseline: 1.7934x; 1.7934x over previous
#include <cuda_runtime.h>
#include <cuda_fp16.h>

#define NMAX_NODES 50000
#define NMAX_EDGES 800000

// Scratch (device globals; no allocation allowed)
__device__ __half g_zh[NMAX_NODES * 128];
__device__ float  g_ssrc[NMAX_NODES];
__device__ float  g_sdst[NMAX_NODES];
__device__ float  g_se[NMAX_EDGES];
__device__ int    g_deg[NMAX_NODES];
__device__ int    g_start[NMAX_NODES];
__device__ int    g_cursor[NMAX_NODES];
__device__ int    g_blocksum[256];
__device__ uint2  g_pe[NMAX_EDGES];   // packed (src, ssrc[src]+s_e), dst-sorted

__device__ __forceinline__ float warp_sum(float v) {
#pragma unroll
    for (int o = 16; o; o >>= 1) v += __shfl_xor_sync(0xffffffffu, v, o);
    return v;
}

__device__ __forceinline__ unsigned smem_u32(const void* p) {
    unsigned a;
    asm("{ .reg .u64 t; cvta.to.shared.u64 t, %1; cvt.u32.u64 %0, t; }"
        : "=r"(a) : "l"(p));
    return a;
}

__device__ __forceinline__ void ldsm_x4(unsigned& r0, unsigned& r1, unsigned& r2,
                                        unsigned& r3, unsigned addr) {
    asm volatile("ldmatrix.sync.aligned.m8n8.x4.shared.b16 {%0,%1,%2,%3}, [%4];"
                 : "=r"(r0), "=r"(r1), "=r"(r2), "=r"(r3) : "r"(addr));
}
__device__ __forceinline__ void ldsm_x2(unsigned& r0, unsigned& r1, unsigned addr) {
    asm volatile("ldmatrix.sync.aligned.m8n8.x2.shared.b16 {%0,%1}, [%2];"
                 : "=r"(r0), "=r"(r1) : "r"(addr));
}
__device__ __forceinline__ void mma16816(float* c, const unsigned* a, const unsigned* b) {
    asm volatile(
        "mma.sync.aligned.m16n8k16.row.col.f32.f16.f16.f32 "
        "{%0,%1,%2,%3}, {%4,%5,%6,%7}, {%8,%9}, {%0,%1,%2,%3};"
        : "+f"(c[0]), "+f"(c[1]), "+f"(c[2]), "+f"(c[3])
        : "r"(a[0]), "r"(a[1]), "r"(a[2]), "r"(a[3]), "r"(b[0]), "r"(b[1]));
}

__device__ __forceinline__ unsigned pack_h2(float a, float b) {
    __half2 h = __floats2half2_rn(a, b);
    return *reinterpret_cast<unsigned*>(&h);
}

// ---------------------------------------------------------------------------
// K1: z = nfeats @ W_fc^T via HMMA, fp32 inputs converted inline.
// Fused epilogue: fp16 z, s_src/s_dst dots, AND deg zeroing.
// ---------------------------------------------------------------------------
#define ASTR 136                 // padded row stride in halfs
#define GEMMH_SMEM (2 * 128 * ASTR * 2 + 288 * 4)

__global__ __launch_bounds__(256) void k_gemm_h(const float* __restrict__ nf,
                                                const float* __restrict__ W,
                                                const float* __restrict__ Wa,
                                                int n_nodes) {
    extern __shared__ __half hsm[];
    __half* sA = hsm;             // [128][ASTR]
    __half* sB = hsm + 128 * ASTR;
    float* sWa = reinterpret_cast<float*>(hsm + 2 * 128 * ASTR);  // [288]
    int tid = threadIdx.x;
    int rowBase = blockIdx.x * 128;

    if (tid < 144) {
        ((float2*)sWa)[tid] = ((const float2*)Wa)[tid];  // 288 floats
    }
#pragma unroll
    for (int c = tid; c < 2048; c += 256) {
        int row = c >> 4;
        int col16 = c & 15;                 // 8-half chunk
        int r = rowBase + row;
        uint4 hv = make_uint4(0u, 0u, 0u, 0u);
        if (r < n_nodes) {
            float4 v0 = ((const float4*)nf)[(size_t)r * 32 + col16 * 2];
            float4 v1 = ((const float4*)nf)[(size_t)r * 32 + col16 * 2 + 1];
            hv.x = pack_h2(v0.x, v0.y);
            hv.y = pack_h2(v0.z, v0.w);
            hv.z = pack_h2(v1.x, v1.y);
            hv.w = pack_h2(v1.z, v1.w);
        }
        *reinterpret_cast<uint4*>(sA + row * ASTR + col16 * 8) = hv;
        float4 w0 = ((const float4*)W)[row * 32 + col16 * 2];
        float4 w1 = ((const float4*)W)[row * 32 + col16 * 2 + 1];
        uint4 wv;
        wv.x = pack_h2(w0.x, w0.y);
        wv.y = pack_h2(w0.z, w0.w);
        wv.z = pack_h2(w1.x, w1.y);
        wv.w = pack_h2(w1.z, w1.w);
        *reinterpret_cast<uint4*>(sB + row * ASTR + col16 * 8) = wv;
    }
    __syncthreads();

    int warp = tid >> 5;
    int lane = tid & 31;
    int m0 = warp * 16;

    float acc[16][4];
#pragma unroll
    for (int nt = 0; nt < 16; nt++)
#pragma unroll
        for (int j = 0; j < 4; j++) acc[nt][j] = 0.f;

    unsigned aBase = smem_u32(sA) + ((m0 + (lane & 15)) * ASTR + ((lane >> 4) << 3)) * 2;
    unsigned bBase = smem_u32(sB) + ((lane & 7) * ASTR + (((lane >> 3) & 1) << 3)) * 2;

#pragma unroll
    for (int ks = 0; ks < 8; ks++) {
        unsigned a[4];
        ldsm_x4(a[0], a[1], a[2], a[3], aBase + ks * 32);
#pragma unroll
        for (int nt = 0; nt < 16; nt++) {
            unsigned b[2];
            ldsm_x2(b[0], b[1], bBase + (nt * 8 * ASTR) * 2 + ks * 32);
            mma16816(acc[nt], a, b);
        }
    }

    // Epilogue: z (fp16) + fused s_src/s_dst partial dots + deg zeroing
    int gr = lane >> 2;
    int colq = (lane & 3) * 2;
    int r0 = rowBase + m0 + gr;
    int r1 = r0 + 8;
    float v1a = 0.f, v2a = 0.f, v1b = 0.f, v2b = 0.f;
#pragma unroll
    for (int nt = 0; nt < 16; nt++) {
        int col = nt * 8 + colq;
        float as0 = sWa[col], as1 = sWa[col + 1];
        float ad0 = sWa[160 + col], ad1 = sWa[161 + col];
        v1a += acc[nt][0] * as0 + acc[nt][1] * as1;
        v2a += acc[nt][0] * ad0 + acc[nt][1] * ad1;
        v1b += acc[nt][2] * as0 + acc[nt][3] * as1;
        v2b += acc[nt][2] * ad0 + acc[nt][3] * ad1;
        if (r0 < n_nodes) {
            unsigned h = pack_h2(acc[nt][0], acc[nt][1]);
            *reinterpret_cast<unsigned*>(g_zh + (size_t)r0 * 128 + col) = h;
        }
        if (r1 < n_nodes) {
            unsigned h = pack_h2(acc[nt][2], acc[nt][3]);
            *reinterpret_cast<unsigned*>(g_zh + (size_t)r1 * 128 + col) = h;
        }
    }
#pragma unroll
    for (int o = 1; o <= 2; o <<= 1) {
        v1a += __shfl_xor_sync(0xffffffffu, v1a, o);
        v2a += __shfl_xor_sync(0xffffffffu, v2a, o);
        v1b += __shfl_xor_sync(0xffffffffu, v1b, o);
        v2b += __shfl_xor_sync(0xffffffffu, v2b, o);
    }
    if ((lane & 3) == 0) {
        if (r0 < n_nodes) { g_ssrc[r0] = v1a; g_sdst[r0] = v2a; g_deg[r0] = 0; }
        if (r1 < n_nodes) { g_ssrc[r1] = v1b; g_sdst[r1] = v2b; g_deg[r1] = 0; }
    }
}

// ---------------------------------------------------------------------------
// K2: coalesced s_e = efeats·a_e + deg histogram. Warp = 32 edges (MLP=8).
// ---------------------------------------------------------------------------
__global__ __launch_bounds__(256) void k_se_hist(const float* __restrict__ ef,
                                                 const float* __restrict__ Wa,
                                                 const int* __restrict__ dst,
                                                 int n_edges) {
    __shared__ float sa[32];
    if (threadIdx.x < 32) sa[threadIdx.x] = Wa[128 + threadIdx.x];  // a_e
    __syncthreads();
    int warp = (blockIdx.x * blockDim.x + threadIdx.x) >> 5;
    int lane = threadIdx.x & 31;
    int sub = lane >> 3;
    int g = lane & 7;
    int e0 = warp * 32 + sub;

    float4 x[8];
#pragma unroll
    for (int u = 0; u < 8; u++) {
        int e = e0 + u * 4;
        x[u] = (e < n_edges) ? __ldg((const float4*)ef + (size_t)e * 8 + g)
                             : make_float4(0.f, 0.f, 0.f, 0.f);
    }
    float c0 = sa[g * 4], c1 = sa[g * 4 + 1], c2 = sa[g * 4 + 2], c3 = sa[g * 4 + 3];
    float v[8];
#pragma unroll
    for (int u = 0; u < 8; u++)
        v[u] = x[u].x * c0 + x[u].y * c1 + x[u].z * c2 + x[u].w * c3;
#pragma unroll
    for (int u = 0; u < 8; u++) {
        v[u] += __shfl_xor_sync(0xffffffffu, v[u], 4);
        v[u] += __shfl_xor_sync(0xffffffffu, v[u], 2);
        v[u] += __shfl_xor_sync(0xffffffffu, v[u], 1);
    }
    if (g == 0) {
#pragma unroll
        for (int u = 0; u < 8; u++) {
            int e = e0 + u * 4;
            if (e < n_edges) {
                g_se[e] = v[u];
                atomicAdd(&g_deg[dst[e]], 1);
            }
        }
    }
}

// ---------------------------------------------------------------------------
// K3a/b/c: exclusive prefix scan of deg -> start/cursor (proven 3-kernel form)
// ---------------------------------------------------------------------------
__global__ void k_scan1(int n) {
    __shared__ int s[256];
    int i = blockIdx.x * 256 + threadIdx.x;
    int v = (i < n) ? g_deg[i] : 0;
    s[threadIdx.x] = v;
    __syncthreads();
#pragma unroll
    for (int off = 1; off < 256; off <<= 1) {
        int t = (threadIdx.x >= off) ? s[threadIdx.x - off] : 0;
        __syncthreads();
        s[threadIdx.x] += t;
        __syncthreads();
    }
    if (i < n) g_start[i] = s[threadIdx.x] - v;
    if (threadIdx.x == 255) g_blocksum[blockIdx.x] = s[255];
}

__global__ void k_scan2(int nb) {
    __shared__ int s[256];
    int v = (threadIdx.x < nb) ? g_blocksum[threadIdx.x] : 0;
    s[threadIdx.x] = v;
    __syncthreads();
#pragma unroll
    for (int off = 1; off < 256; off <<= 1) {
        int t = (threadIdx.x >= off) ? s[threadIdx.x - off] : 0;
        __syncthreads();
        s[threadIdx.x] += t;
        __syncthreads();
    }
    if (threadIdx.x < nb) g_blocksum[threadIdx.x] = s[threadIdx.x] - v;
}

__global__ void k_scan3(int n) {
    int i = blockIdx.x * 256 + threadIdx.x;
    if (i < n) {
        int st = g_start[i] + g_blocksum[blockIdx.x];
        g_start[i] = st;
        g_cursor[i] = st;
    }
}

// ---------------------------------------------------------------------------
// K4: per edge: t = ssrc[src] + s_e; place packed (src, t) into dst-sorted
//     position. 2 edges per thread, front-batched loads (MLP x2).
// ---------------------------------------------------------------------------
__global__ __launch_bounds__(256) void k_edge_place(const int* __restrict__ src,
                                                    const int* __restrict__ dst,
                                                    int n_edges) {
    int base = (blockIdx.x * blockDim.x + threadIdx.x) * 2;
    if (base >= n_edges) return;
    int e0 = base;
    int e1 = base + 1;
    bool ok1 = (e1 < n_edges);

    int s0 = src[e0];
    int d0 = dst[e0];
    float se0 = g_se[e0];
    int s1 = ok1 ? src[e1] : 0;
    int d1 = ok1 ? dst[e1] : 0;
    float se1 = ok1 ? g_se[e1] : 0.f;

    float t0 = __ldg(&g_ssrc[s0]) + se0;
    float t1 = ok1 ? (__ldg(&g_ssrc[s1]) + se1) : 0.f;

    int pos0 = atomicAdd(&g_cursor[d0], 1);
    uint2 v0;
    v0.x = (unsigned)s0;
    v0.y = __float_as_uint(t0);
    g_pe[pos0] = v0;
    if (ok1) {
        int pos1 = atomicAdd(&g_cursor[d1], 1);
        uint2 v1;
        v1.x = (unsigned)s1;
        v1.y = __float_as_uint(t1);
        g_pe[pos1] = v1;
    }
}

// ---------------------------------------------------------------------------
// K5: warp per dst node: w_e = exp(leaky(t_e + sdst[d])) vectorized;
//     h[d] = (sum w_e * zh[src_e]) / (sum w_e). Gather loop unrolled x4.
// ---------------------------------------------------------------------------
__global__ __launch_bounds__(256) void k_agg(float* __restrict__ out, int n_nodes) {
    int d = (blockIdx.x * blockDim.x + threadIdx.x) >> 5;
    int lane = threadIdx.x & 31;
    if (d >= n_nodes) return;
    int start = g_start[d];
    int deg = g_deg[d];
    float sdst_d = g_sdst[d];
    float4 acc = make_float4(0.f, 0.f, 0.f, 0.f);
    float wsum = 0.f;

    for (int i = 0; i < deg; i += 32) {
        int s = 0;
        float wv = 0.f;
        if (i + lane < deg) {
            uint2 p = g_pe[start + i + lane];
            s = (int)p.x;
            float ev = __uint_as_float(p.y) + sdst_d;
            ev = (ev > 0.f) ? ev : 0.01f * ev;
            wv = __expf(ev);
        }
        wsum += wv;
        int cnt = min(32, deg - i);
        int j = 0;
        for (; j + 4 <= cnt; j += 4) {
            int s0 = __shfl_sync(0xffffffffu, s, j);
            int s1 = __shfl_sync(0xffffffffu, s, j + 1);
            int s2 = __shfl_sync(0xffffffffu, s, j + 2);
            int s3 = __shfl_sync(0xffffffffu, s, j + 3);
            float w0 = __shfl_sync(0xffffffffu, wv, j);
            float w1 = __shfl_sync(0xffffffffu, wv, j + 1);
            float w2 = __shfl_sync(0xffffffffu, wv, j + 2);
            float w3 = __shfl_sync(0xffffffffu, wv, j + 3);
            uint2 h0 = *reinterpret_cast<const uint2*>(g_zh + (size_t)s0 * 128 + lane * 4);
            uint2 h1 = *reinterpret_cast<const uint2*>(g_zh + (size_t)s1 * 128 + lane * 4);
            uint2 h2 = *reinterpret_cast<const uint2*>(g_zh + (size_t)s2 * 128 + lane * 4);
            uint2 h3 = *reinterpret_cast<const uint2*>(g_zh + (size_t)s3 * 128 + lane * 4);
#define ACC_EDGE(hz, wj)                                                   \
            {                                                              \
                float2 f01 = __half22float2(*reinterpret_cast<__half2*>(&hz.x)); \
                float2 f23 = __half22float2(*reinterpret_cast<__half2*>(&hz.y)); \
                acc.x += (wj) * f01.x;                                     \
                acc.y += (wj) * f01.y;                                     \
                acc.z += (wj) * f23.x;                                     \
                acc.w += (wj) * f23.y;                                     \
            }
            ACC_EDGE(h0, w0)
            ACC_EDGE(h1, w1)
            ACC_EDGE(h2, w2)
            ACC_EDGE(h3, w3)
        }
        for (; j < cnt; j++) {
            int sj = __shfl_sync(0xffffffffu, s, j);
            float wj = __shfl_sync(0xffffffffu, wv, j);
            uint2 hz = *reinterpret_cast<const uint2*>(g_zh + (size_t)sj * 128 + lane * 4);
            ACC_EDGE(hz, wj)
        }
#undef ACC_EDGE
    }
    wsum = warp_sum(wsum);
    float dinv = (wsum > 0.f) ? 1.0f / wsum : 0.f;
    ((float4*)out)[d * 32 + lane] =
        make_float4(acc.x * dinv, acc.y * dinv, acc.z * dinv, acc.w * dinv);
}

// ---------------------------------------------------------------------------
extern "C" void kernel_launch(void* const* d_in, const int* in_sizes, int n_in,
                              void* d_out, int out_size) {
    const float* nf  = (const float*)d_in[0];
    const float* ef  = (const float*)d_in[1];
    const float* Wfc = (const float*)d_in[2];
    const float* Wa  = (const float*)d_in[3];
    const int*   src = (const int*)d_in[4];
    const int*   dst = (const int*)d_in[5];
    float* out = (float*)d_out;

    int n_nodes = in_sizes[0] / 128;
    int n_edges = in_sizes[4];
    int nscan = (n_nodes + 255) / 256;  // 196 (<= 256)

    cudaFuncSetAttribute(k_gemm_h, cudaFuncAttributeMaxDynamicSharedMemorySize, GEMMH_SMEM);

    k_gemm_h<<<(n_nodes + 127) / 128, 256, GEMMH_SMEM>>>(nf, Wfc, Wa, n_nodes);
    k_se_hist<<<(n_edges + 255) / 256, 256>>>(ef, Wa, dst, n_edges);
    k_scan1<<<nscan, 256>>>(n_nodes);
    k_scan2<<<1, 256>>>(nscan);
    k_scan3<<<nscan, 256>>>(n_nodes);
    k_edge_place<<<(n_edges + 511) / 512, 256>>>(src, dst, n_edges);
    k_agg<<<(n_nodes + 7) / 8, 256>>>(out, n_nodes);
}